// round 15
// baseline (speedup 1.0000x reference)
#include <cuda_runtime.h>
#include <math.h>

#define Bc 8
#define Nc 1024
#define Mc 20000
#define Cc 80
#define Gc 64
#define NMS_THRf 0.5f
#define EPSf 1e-6f
#define FULL 0xffffffffu

#define NT 512      // nms_loss block size

// per-batch results: [b*2+0]=push_b, [b*2+1]=pull_b
__device__ float g_partial[Bc * 2];
__device__ int   g_done;
// adjacency bitmasks in RANK space, LOWER TRIANGLE only:
// row r, words w <= r>>5 valid; word w bit s <-> rank (w<<5)|s
__device__ unsigned g_adj[Bc * Nc * 32];
// gathered scores in ORIGINAL index space (linear)
__device__ float g_scores_orig[Bc * Nc];
// rank-permuted scores: g_scores[b][rank]
__device__ float g_scores[Bc * Nc];
// permutation: g_perm[b][rank] = original index
__device__ int g_perm[Bc * Nc];

__device__ __forceinline__ float iou_legacy(float4 a, float4 b, float area_a, float area_b) {
    float lx = fmaxf(a.x, b.x), ly = fmaxf(a.y, b.y);
    float rx = fminf(a.z, b.z), ry = fminf(a.w, b.w);
    float w = fmaxf(rx - lx + 1.0f, 0.0f), h = fmaxf(ry - ly + 1.0f, 0.0f);
    float ov = w * h;
    return ov / (area_a + area_b - ov);
}

// ---------------- score gather: one pass, high MLP ----------------
__global__ __launch_bounds__(256)
void gather_kernel(const int* __restrict__ pos_inds,
                   const int* __restrict__ pos_gt_index,
                   const float* __restrict__ cls_scores,
                   const int* __restrict__ gt_labels)
{
    const int b = blockIdx.x;
    const int tid = threadIdx.x;
    if (b == 0 && tid == 0) g_done = 0;
    int pi[4], gi[4];
    #pragma unroll
    for (int k = 0; k < 4; k++) {
        int n = tid + (k << 8);
        pi[k] = pos_inds[b * Nc + n];
        gi[k] = pos_gt_index[b * Nc + n];
    }
    int lbl[4];
    #pragma unroll
    for (int k = 0; k < 4; k++) lbl[k] = gt_labels[b * Gc + gi[k]];
    #pragma unroll
    for (int k = 0; k < 4; k++) {
        int n = tid + (k << 8);
        g_scores_orig[(b << 10) + n] =
            cls_scores[((size_t)b * Mc + pi[k]) * Cc + lbl[k]];
    }
}

// ---------------- rank: 32 blocks per batch, 4 rows per warp ----------------
__global__ __launch_bounds__(256)
void rank_kernel(void)
{
    __shared__ float ssc[Nc];
    const int b = blockIdx.y;
    {
        const float4* src = (const float4*)(g_scores_orig + (b << 10));
        float4* dst = (float4*)ssc;
        for (int p = threadIdx.x; p < Nc / 4; p += 256) dst[p] = src[p];
    }
    __syncthreads();

    const int wid = threadIdx.x >> 5, lane = threadIdx.x & 31;
    #pragma unroll
    for (int t = 0; t < 4; t++) {
        const int i = blockIdx.x * 32 + wid * 4 + t;
        const float si = ssc[i];
        int cnt = 0;
        #pragma unroll
        for (int w = 0; w < 32; w++) {
            int n = (w << 5) | lane;        // coalesced, conflict-free
            float sn = ssc[n];
            cnt += (sn > si) || (sn == si && n < i);
        }
        cnt = __reduce_add_sync(FULL, cnt);
        if (lane == 0) {
            g_perm[(b << 10) + cnt] = i;    // unique ranks -> no conflicts
            g_scores[(b << 10) + cnt] = si; // rank-permuted scores
        }
    }
}

// ---------------- lower-tri adjacency: 4 striped rows per warp ----------------
__global__ __launch_bounds__(256)
void adj_kernel(const float* __restrict__ bbox_preds)
{
    __shared__ float4 sb[Nc];
    __shared__ float  sa[Nc];
    const int b = blockIdx.y;
    const float4* bp = (const float4*)(bbox_preds + (size_t)b * Nc * 4);
    for (int n = threadIdx.x; n < Nc; n += 256) {
        int orig = g_perm[(b << 10) + n];
        float4 bx = bp[orig];
        sb[n] = bx;
        sa[n] = (bx.z - bx.x + 1.0f) * (bx.w - bx.y + 1.0f);
    }
    __syncthreads();

    const int wid = threadIdx.x >> 5, lane = threadIdx.x & 31;
    #pragma unroll
    for (int t = 0; t < 4; t++) {
        const int i = blockIdx.x * 8 + wid + (t << 8);   // striped rows: balance
        const int wi = i >> 5;
        const float4 bi = sb[i];
        const float ai = sa[i];
        unsigned* dst = g_adj + ((((size_t)b << 10) + i) << 5);
        for (int w = 0; w <= wi; w++) {     // lower triangle only
            int n = (w << 5) | lane;        // coalesced, conflict-free
            float v = iou_legacy(bi, sb[n], ai, sa[n]);
            unsigned bal = __ballot_sync(FULL, v > NMS_THRf && n != i);
            if (lane == 0) dst[w] = bal;
        }
    }
}

// ---------------- fixpoint + parallel loss: 1 block (512 thr) per batch ----------------
// Adjacency is read DIRECTLY from g_adj (L2 round 1, L1-hot afterwards) —
// no smem staging copy.
// dynamic smem layout (bytes):
//   sboxA   float4[1024] @ 0       box coords                (16384)
//   sboxB   float4[1024] @ 16384   (area, score, gt, -)      (16384)
//   sgtiou  float[64*64] @ 32768                             (16384)
//   skiller int[1024]    @ 49152                             (4096)
//   snpush  int[1024]    @ 53248                             (4096)
//   sfirst  int[64]      @ 57344                             (256)
//   skeptM  u32[32]      @ 57600                             (128)
//   sdeadM  u32[32]      @ 57728                             (128)
#define SMEM_BYTES 57856

extern __shared__ unsigned char smem_raw[];

__global__ __launch_bounds__(NT, 1)
void nms_loss_kernel(const int* __restrict__ pos_gt_index,
                     const float* __restrict__ gt_bboxes,
                     const float* __restrict__ bbox_preds,
                     float* __restrict__ out)
{
    float4*   sboxA   = (float4*)(smem_raw);
    float4*   sboxB   = (float4*)(smem_raw + 16384);
    float*    sgtiou  = (float*)(smem_raw + 32768);
    int*      skiller = (int*)(smem_raw + 49152);
    int*      snpush  = (int*)(smem_raw + 53248);
    int*      sfirst  = (int*)(smem_raw + 57344);
    unsigned* skeptM  = (unsigned*)(smem_raw + 57600);
    unsigned* sdeadM  = (unsigned*)(smem_raw + 57728);

    __shared__ int   s_lastr;
    __shared__ float s_pull, s_push;
    __shared__ int   s_pcnt, s_qcnt;

    const int b = blockIdx.x;
    const int tid = threadIdx.x;
    const unsigned* adjb = g_adj + ((size_t)b << 15);   // row r word w: adjb[(r<<5)+w]

    // ---- setup: permuted arrays by rank ----
    const float4* bp = (const float4*)(bbox_preds + (size_t)b * Nc * 4);
    for (int r = tid; r < Nc; r += NT) {
        int orig = g_perm[(b << 10) + r];
        float4 bx = bp[orig];
        sboxA[r] = bx;
        float area = (bx.z - bx.x + 1.0f) * (bx.w - bx.y + 1.0f);
        float sc = g_scores[(b << 10) + r];           // rank-permuted already
        int gi = pos_gt_index[b * Nc + orig];
        sboxB[r] = make_float4(area, sc, __int_as_float(gi), 0.0f);
        snpush[r] = 0;
    }
    const float4* gb = (const float4*)(gt_bboxes + (size_t)b * Gc * 4);
    for (int p = tid; p < Gc * Gc; p += NT) {
        int g1 = p >> 6, g2 = p & 63;
        float4 a = gb[g1];
        float4 c = gb[g2];
        float a1 = (a.z - a.x + 1.0f) * (a.w - a.y + 1.0f);
        float a2 = (c.z - c.x + 1.0f) * (c.w - c.y + 1.0f);
        sgtiou[p] = iou_legacy(a, c, a1, a2);
    }
    for (int g = tid; g < Gc; g += NT) sfirst[g] = 1 << 30;
    if (tid < 32) { skeptM[tid] = 0u; sdeadM[tid] = 0u; }
    if (tid == 0) { s_pull = 0.0f; s_push = 0.0f; s_pcnt = 0; s_qcnt = 0; }
    __syncthreads();

    // ---- Phase 1: parallel-round NMS fixpoint, adjacency straight from L2/L1 ----
    // n DEAD <=> some KEPT lower-rank neighbor; n KEPT <=> all lower dead.
    {
        bool decided[2] = {false, false};
        while (true) {
            #pragma unroll
            for (int k = 0; k < 2; k++) {
                if (decided[k]) continue;
                int n = tid + (k << 9);
                int wn = n >> 5, sn = n & 31;
                const unsigned* row = adjb + (n << 5);
                unsigned dead_or = 0u, undec_or = 0u;
                for (int w = 0; w < wn; w++) {           // independent loads
                    unsigned r = __ldg(row + w);
                    unsigned kp = skeptM[w], dd = sdeadM[w];
                    dead_or  |= r & kp;
                    undec_or |= r & ~(kp | dd);
                }
                {                                         // partial word wn
                    unsigned r = __ldg(row + wn) & (sn ? ((1u << sn) - 1u) : 0u);
                    unsigned kp = skeptM[wn], dd = sdeadM[wn];
                    dead_or  |= r & kp;
                    undec_or |= r & ~(kp | dd);
                }
                if (dead_or) {
                    atomicOr(&sdeadM[wn], 1u << sn);
                    decided[k] = true;
                } else if (!undec_or) {
                    atomicOr(&skeptM[wn], 1u << sn);
                    decided[k] = true;
                }
            }
            // one barrier per round: termination test + fence for mask writes
            if (!__syncthreads_or((!decided[0]) || (!decided[1]))) break;
        }
    }
    if (tid == 0) {                          // lastr = highest-rank kept box
        int lastr = 0;
        for (int w = 31; w >= 0; w--) {
            if (skeptM[w]) { lastr = (w << 5) | (31 - __clz(skeptM[w])); break; }
        }
        s_lastr = lastr;
    }
    __syncthreads();

    const int lastr = s_lastr;

    // ---- Phase 2a: recover killer(n) (lower words, L1-hot); per-gt first; histogram ----
    // killer(n) = lowest-rank kept neighbor, always < n for dead boxes; kept
    // boxes have no kept neighbors at all (independent set, symmetric adj).
    int pred_last = 0;
    for (int n = tid; n < Nc; n += NT) {
        int x_wn = n >> 5;
        const unsigned* row = adjb + (n << 5);
        unsigned nz = 0u;
        for (int w = 0; w <= x_wn; w++) {    // independent L1-hot loads
            unsigned m = __ldg(row + w) & skeptM[w];
            nz |= (m != 0u) ? (1u << w) : 0u;
        }
        int kr = -1;
        if (nz) {
            int w = __ffs(nz) - 1;
            unsigned m = __ldg(row + w) & skeptM[w];
            kr = (w << 5) | (__ffs(m) - 1);
        }
        skiller[n] = kr;
        if (kr < 0) {
            int g = __float_as_int(sboxB[n].z);
            atomicMin(&sfirst[g], n);
        } else {
            if (kr == lastr) pred_last = 1;
            int g = __float_as_int(sboxB[kr].z);
            int gn = __float_as_int(sboxB[n].z);
            if (gn != g) {
                float iouv = iou_legacy(sboxA[kr], sboxA[n], sboxB[kr].x, sboxB[n].x);
                if (iouv > sgtiou[(g << 6) + gn]) atomicAdd(&snpush[kr], 1);
            }
        }
    }
    int last_rem = __syncthreads_or(pred_last);   // barrier + OR

    // ---- Phase 2b: accumulate pull/push in parallel ----
    float lpull = 0.0f, lpush = 0.0f;
    int lpc = 0, lqc = 0;
    for (int n = tid; n < Nc; n += NT) {
        int kr = skiller[n];
        if (kr < 0) {
            int g = __float_as_int(sboxB[n].z);
            int prev = sfirst[g];
            if (prev < n) {
                lpc++;                                     // pcnt is ungated
                if (!(n == lastr && !last_rem)) {
                    float ms = fmaxf(iou_legacy(sboxA[prev], sboxA[n],
                                                sboxB[prev].x, sboxB[n].x), EPSf);
                    lpull += -__logf(1.0f - NMS_THRf + ms) * sboxB[n].y;
                }
            }
        } else {
            int g = __float_as_int(sboxB[kr].z);
            int gn = __float_as_int(sboxB[n].z);
            if (gn != g) {
                float iouv = iou_legacy(sboxA[kr], sboxA[n], sboxB[kr].x, sboxB[n].x);
                if (iouv > sgtiou[(g << 6) + gn]) {
                    lqc++;
                    lpush += -__logf(1.0f - iouv) * sboxB[n].y / (float)snpush[kr];
                }
            }
        }
    }
    #pragma unroll
    for (int off = 16; off > 0; off >>= 1) {
        lpull += __shfl_xor_sync(FULL, lpull, off);
        lpush += __shfl_xor_sync(FULL, lpush, off);
        lpc   += __shfl_xor_sync(FULL, lpc, off);
        lqc   += __shfl_xor_sync(FULL, lqc, off);
    }
    if ((tid & 31) == 0) {
        atomicAdd(&s_pull, lpull);
        atomicAdd(&s_push, lpush);
        atomicAdd(&s_pcnt, lpc);
        atomicAdd(&s_qcnt, lqc);
    }
    __syncthreads();

    // ---- finalize: last block sums per-batch partials ----
    if (tid == 0) {
        g_partial[b * 2 + 0] = s_push / ((float)s_qcnt + EPSf);
        g_partial[b * 2 + 1] = s_pull / ((float)s_pcnt + EPSf);
        __threadfence();
        int prev = atomicAdd(&g_done, 1);
        if (prev == Bc - 1) {
            float sp = 0.0f, sl = 0.0f;
            #pragma unroll
            for (int bb = 0; bb < Bc; bb++) {
                sp += *((volatile float*)&g_partial[bb * 2 + 0]);
                sl += *((volatile float*)&g_partial[bb * 2 + 1]);
            }
            out[0] = sp / (float)Bc;   // mean(push) * PUSH_W
            out[1] = sl / (float)Bc;   // mean(pull) * PULL_W
        }
    }
}

extern "C" void kernel_launch(void* const* d_in, const int* in_sizes, int n_in,
                              void* d_out, int out_size) {
    const int*   pos_inds     = (const int*)d_in[0];
    const int*   pos_gt_index = (const int*)d_in[1];
    const float* gt_bboxes    = (const float*)d_in[2];
    const float* bbox_preds   = (const float*)d_in[3];
    const float* cls_scores   = (const float*)d_in[4];
    const int*   gt_labels    = (const int*)d_in[5];
    float* out = (float*)d_out;

    cudaFuncSetAttribute(nms_loss_kernel,
                         cudaFuncAttributeMaxDynamicSharedMemorySize, SMEM_BYTES);

    gather_kernel<<<Bc, 256>>>(pos_inds, pos_gt_index, cls_scores, gt_labels);
    rank_kernel<<<dim3(32, Bc), 256>>>();
    adj_kernel<<<dim3(32, Bc), 256>>>(bbox_preds);
    nms_loss_kernel<<<Bc, NT, SMEM_BYTES>>>(pos_gt_index, gt_bboxes, bbox_preds, out);
}

// round 16
// speedup vs baseline: 1.2406x; 1.2406x over previous
#include <cuda_runtime.h>
#include <math.h>

#define Bc 8
#define Nc 1024
#define Mc 20000
#define Cc 80
#define Gc 64
#define NMS_THRf 0.5f
#define EPSf 1e-6f
#define FULL 0xffffffffu

#define NT 512      // nms_loss block size

// per-batch results: [b*2+0]=push_b, [b*2+1]=pull_b
__device__ float g_partial[Bc * 2];
__device__ int   g_done;
// adjacency bitmasks in RANK space, LOWER TRIANGLE only:
// row r, words w <= r>>5 valid; word w bit s <-> rank (w<<5)|s
__device__ unsigned g_adj[Bc * Nc * 32];
// gathered scores in ORIGINAL index space (linear)
__device__ float g_scores_orig[Bc * Nc];
// rank-permuted scores: g_scores[b][rank]
__device__ float g_scores[Bc * Nc];
// permutation: g_perm[b][rank] = original index
__device__ int g_perm[Bc * Nc];

__device__ __forceinline__ float iou_legacy(float4 a, float4 b, float area_a, float area_b) {
    float lx = fmaxf(a.x, b.x), ly = fmaxf(a.y, b.y);
    float rx = fminf(a.z, b.z), ry = fminf(a.w, b.w);
    float w = fmaxf(rx - lx + 1.0f, 0.0f), h = fmaxf(ry - ly + 1.0f, 0.0f);
    float ov = w * h;
    return ov / (area_a + area_b - ov);
}

// ---------------- score gather: one pass, high MLP ----------------
__global__ __launch_bounds__(256)
void gather_kernel(const int* __restrict__ pos_inds,
                   const int* __restrict__ pos_gt_index,
                   const float* __restrict__ cls_scores,
                   const int* __restrict__ gt_labels)
{
    const int b = blockIdx.x;
    const int tid = threadIdx.x;
    if (b == 0 && tid == 0) g_done = 0;
    int pi[4], gi[4];
    #pragma unroll
    for (int k = 0; k < 4; k++) {
        int n = tid + (k << 8);
        pi[k] = pos_inds[b * Nc + n];
        gi[k] = pos_gt_index[b * Nc + n];
    }
    int lbl[4];
    #pragma unroll
    for (int k = 0; k < 4; k++) lbl[k] = gt_labels[b * Gc + gi[k]];
    #pragma unroll
    for (int k = 0; k < 4; k++) {
        int n = tid + (k << 8);
        g_scores_orig[(b << 10) + n] =
            cls_scores[((size_t)b * Mc + pi[k]) * Cc + lbl[k]];
    }
}

// ---------------- rank: 32 blocks per batch, 4 rows per warp ----------------
__global__ __launch_bounds__(256)
void rank_kernel(void)
{
    __shared__ float ssc[Nc];
    const int b = blockIdx.y;
    {
        const float4* src = (const float4*)(g_scores_orig + (b << 10));
        float4* dst = (float4*)ssc;
        for (int p = threadIdx.x; p < Nc / 4; p += 256) dst[p] = src[p];
    }
    __syncthreads();

    const int wid = threadIdx.x >> 5, lane = threadIdx.x & 31;
    #pragma unroll
    for (int t = 0; t < 4; t++) {
        const int i = blockIdx.x * 32 + wid * 4 + t;
        const float si = ssc[i];
        int cnt = 0;
        #pragma unroll
        for (int w = 0; w < 32; w++) {
            int n = (w << 5) | lane;        // coalesced, conflict-free
            float sn = ssc[n];
            cnt += (sn > si) || (sn == si && n < i);
        }
        cnt = __reduce_add_sync(FULL, cnt);
        if (lane == 0) {
            g_perm[(b << 10) + cnt] = i;    // unique ranks -> no conflicts
            g_scores[(b << 10) + cnt] = si; // rank-permuted scores
        }
    }
}

// ---------------- lower-tri adjacency: 4 striped rows per warp ----------------
__global__ __launch_bounds__(256)
void adj_kernel(const float* __restrict__ bbox_preds)
{
    __shared__ float4 sb[Nc];
    __shared__ float  sa[Nc];
    const int b = blockIdx.y;
    const float4* bp = (const float4*)(bbox_preds + (size_t)b * Nc * 4);
    for (int n = threadIdx.x; n < Nc; n += 256) {
        int orig = g_perm[(b << 10) + n];
        float4 bx = bp[orig];
        sb[n] = bx;
        sa[n] = (bx.z - bx.x + 1.0f) * (bx.w - bx.y + 1.0f);
    }
    __syncthreads();

    const int wid = threadIdx.x >> 5, lane = threadIdx.x & 31;
    #pragma unroll
    for (int t = 0; t < 4; t++) {
        const int i = blockIdx.x * 8 + wid + (t << 8);   // striped rows: balance
        const int wi = i >> 5;
        const float4 bi = sb[i];
        const float ai = sa[i];
        unsigned* dst = g_adj + ((((size_t)b << 10) + i) << 5);
        for (int w = 0; w <= wi; w++) {     // lower triangle only
            int n = (w << 5) | lane;        // coalesced, conflict-free
            float v = iou_legacy(bi, sb[n], ai, sa[n]);
            unsigned bal = __ballot_sync(FULL, v > NMS_THRf && n != i);
            if (lane == 0) dst[w] = bal;
        }
    }
}

// ---------------- fixpoint + parallel loss: 1 block (512 thr) per batch ----------------
// smem adjacency is bank-swizzled: word w of row r lives at sadj[r*32 + (w^(r&31))]
// dynamic smem layout (bytes):
//   sboxA   float4[1024] @ 0       box coords                (16384)
//   sboxB   float4[1024] @ 16384   (area, score, gt, -)      (16384)
//   sadj    u32[1024*32] @ 32768   swizzled, lower-tri valid (131072)
//   sgtiou  float[64*64] @ 163840                            (16384)
//   skiller int[1024]    @ 180224                            (4096)
//   snpush  int[1024]    @ 184320                            (4096)
//   sfirst  int[64]      @ 188416                            (256)
//   skeptM  u32[32]      @ 188672                            (128)
//   sdeadM  u32[32]      @ 188800                            (128)
#define SMEM_BYTES 188928

extern __shared__ unsigned char smem_raw[];

__global__ __launch_bounds__(NT, 1)
void nms_loss_kernel(const int* __restrict__ pos_gt_index,
                     const float* __restrict__ gt_bboxes,
                     const float* __restrict__ bbox_preds,
                     float* __restrict__ out)
{
    float4*   sboxA   = (float4*)(smem_raw);
    float4*   sboxB   = (float4*)(smem_raw + 16384);
    unsigned* sadj    = (unsigned*)(smem_raw + 32768);
    float*    sgtiou  = (float*)(smem_raw + 163840);
    int*      skiller = (int*)(smem_raw + 180224);
    int*      snpush  = (int*)(smem_raw + 184320);
    int*      sfirst  = (int*)(smem_raw + 188416);
    unsigned* skeptM  = (unsigned*)(smem_raw + 188672);
    unsigned* sdeadM  = (unsigned*)(smem_raw + 188800);

    __shared__ int   s_lastr;
    __shared__ float s_pull, s_push;
    __shared__ int   s_pcnt, s_qcnt;

    const int b = blockIdx.x;
    const int tid = threadIdx.x;

    // ---- setup: permuted arrays by rank ----
    const float4* bp = (const float4*)(bbox_preds + (size_t)b * Nc * 4);
    for (int r = tid; r < Nc; r += NT) {
        int orig = g_perm[(b << 10) + r];
        float4 bx = bp[orig];
        sboxA[r] = bx;
        float area = (bx.z - bx.x + 1.0f) * (bx.w - bx.y + 1.0f);
        float sc = g_scores[(b << 10) + r];           // rank-permuted already
        int gi = pos_gt_index[b * Nc + orig];
        sboxB[r] = make_float4(area, sc, __int_as_float(gi), 0.0f);
        snpush[r] = 0;
    }
    const float4* gb = (const float4*)(gt_bboxes + (size_t)b * Gc * 4);
    for (int p = tid; p < Gc * Gc; p += NT) {
        int g1 = p >> 6, g2 = p & 63;
        float4 a = gb[g1];
        float4 c = gb[g2];
        float a1 = (a.z - a.x + 1.0f) * (a.w - a.y + 1.0f);
        float a2 = (c.z - c.x + 1.0f) * (c.w - c.y + 1.0f);
        sgtiou[p] = iou_legacy(a, c, a1, a2);
    }
    for (int g = tid; g < Gc; g += NT) sfirst[g] = 1 << 30;
    // swizzled copy of lower-triangle adjacency (~66KB)
    {
        const uint4* asrc4 = (const uint4*)(g_adj + ((size_t)b << 15));
        for (int idx = tid; idx < Nc * 8; idx += NT) {
            int r = idx >> 3, q = idx & 7;
            if ((q << 2) <= (r >> 5)) {                // quad overlaps lower tri
                uint4 v = asrc4[idx];
                int w0 = q << 2, x = r & 31;
                int base = r << 5;
                sadj[base + ((w0 + 0) ^ x)] = v.x;
                sadj[base + ((w0 + 1) ^ x)] = v.y;
                sadj[base + ((w0 + 2) ^ x)] = v.z;
                sadj[base + ((w0 + 3) ^ x)] = v.w;
            }
        }
    }
    if (tid < 32) { skeptM[tid] = 0u; sdeadM[tid] = 0u; }
    if (tid == 0) { s_pull = 0.0f; s_push = 0.0f; s_pcnt = 0; s_qcnt = 0; }
    __syncthreads();

    // ---- Phase 1: parallel-round NMS fixpoint (512 threads, 2 items each) ----
    // n DEAD <=> some KEPT lower-rank neighbor; n KEPT <=> all lower dead.
    // One barrier per round (__syncthreads_or doubles as termination vote +
    // memory fence); no shared-atomic round counter.
    {
        bool decided[2] = {false, false};
        while (true) {
            #pragma unroll
            for (int k = 0; k < 2; k++) {
                if (decided[k]) continue;
                int n = tid + (k << 9);
                int wn = n >> 5, sn = n & 31;
                int base = n << 5;
                unsigned dead_or = 0u, undec_or = 0u;
                for (int w = 0; w < wn; w++) {           // independent LDS
                    unsigned r = sadj[base + (w ^ sn)];
                    unsigned kp = skeptM[w], dd = sdeadM[w];
                    dead_or  |= r & kp;
                    undec_or |= r & ~(kp | dd);
                }
                {                                         // partial word wn
                    unsigned r = sadj[base + (wn ^ sn)] & (sn ? ((1u << sn) - 1u) : 0u);
                    unsigned kp = skeptM[wn], dd = sdeadM[wn];
                    dead_or  |= r & kp;
                    undec_or |= r & ~(kp | dd);
                }
                if (dead_or) {
                    atomicOr(&sdeadM[wn], 1u << sn);
                    decided[k] = true;
                } else if (!undec_or) {
                    atomicOr(&skeptM[wn], 1u << sn);
                    decided[k] = true;
                }
            }
            if (!__syncthreads_or((!decided[0]) || (!decided[1]))) break;
        }
    }
    if (tid == 0) {                          // lastr = highest-rank kept box
        int lastr = 0;
        for (int w = 31; w >= 0; w--) {
            if (skeptM[w]) { lastr = (w << 5) | (31 - __clz(skeptM[w])); break; }
        }
        s_lastr = lastr;
    }
    __syncthreads();

    const int lastr = s_lastr;

    // ---- Phase 2a: recover killer(n) (lower words only); per-gt first; histogram ----
    // killer(n) = lowest-rank kept neighbor, always < n for dead boxes; kept
    // boxes have no kept neighbors at all (independent set, symmetric adj).
    int pred_last = 0;
    for (int n = tid; n < Nc; n += NT) {
        int base = n << 5, x = n & 31, wn = n >> 5;
        unsigned nz = 0u;
        for (int w = 0; w <= wn; w++) {      // independent conflict-free LDS
            unsigned m = sadj[base + (w ^ x)] & skeptM[w];
            nz |= (m != 0u) ? (1u << w) : 0u;
        }
        int kr = -1;
        if (nz) {
            int w = __ffs(nz) - 1;
            unsigned m = sadj[base + (w ^ x)] & skeptM[w];
            kr = (w << 5) | (__ffs(m) - 1);
        }
        skiller[n] = kr;
        if (kr < 0) {
            int g = __float_as_int(sboxB[n].z);
            atomicMin(&sfirst[g], n);
        } else {
            if (kr == lastr) pred_last = 1;
            int g = __float_as_int(sboxB[kr].z);
            int gn = __float_as_int(sboxB[n].z);
            if (gn != g) {
                float iouv = iou_legacy(sboxA[kr], sboxA[n], sboxB[kr].x, sboxB[n].x);
                if (iouv > sgtiou[(g << 6) + gn]) atomicAdd(&snpush[kr], 1);
            }
        }
    }
    int last_rem = __syncthreads_or(pred_last);   // barrier + OR

    // ---- Phase 2b: accumulate pull/push in parallel ----
    float lpull = 0.0f, lpush = 0.0f;
    int lpc = 0, lqc = 0;
    for (int n = tid; n < Nc; n += NT) {
        int kr = skiller[n];
        if (kr < 0) {
            int g = __float_as_int(sboxB[n].z);
            int prev = sfirst[g];
            if (prev < n) {
                lpc++;                                     // pcnt is ungated
                if (!(n == lastr && !last_rem)) {
                    float ms = fmaxf(iou_legacy(sboxA[prev], sboxA[n],
                                                sboxB[prev].x, sboxB[n].x), EPSf);
                    lpull += -__logf(1.0f - NMS_THRf + ms) * sboxB[n].y;
                }
            }
        } else {
            int g = __float_as_int(sboxB[kr].z);
            int gn = __float_as_int(sboxB[n].z);
            if (gn != g) {
                float iouv = iou_legacy(sboxA[kr], sboxA[n], sboxB[kr].x, sboxB[n].x);
                if (iouv > sgtiou[(g << 6) + gn]) {
                    lqc++;
                    lpush += -__logf(1.0f - iouv) * sboxB[n].y / (float)snpush[kr];
                }
            }
        }
    }
    #pragma unroll
    for (int off = 16; off > 0; off >>= 1) {
        lpull += __shfl_xor_sync(FULL, lpull, off);
        lpush += __shfl_xor_sync(FULL, lpush, off);
        lpc   += __shfl_xor_sync(FULL, lpc, off);
        lqc   += __shfl_xor_sync(FULL, lqc, off);
    }
    if ((tid & 31) == 0) {
        atomicAdd(&s_pull, lpull);
        atomicAdd(&s_push, lpush);
        atomicAdd(&s_pcnt, lpc);
        atomicAdd(&s_qcnt, lqc);
    }
    __syncthreads();

    // ---- finalize: last block sums per-batch partials ----
    if (tid == 0) {
        g_partial[b * 2 + 0] = s_push / ((float)s_qcnt + EPSf);
        g_partial[b * 2 + 1] = s_pull / ((float)s_pcnt + EPSf);
        __threadfence();
        int prev = atomicAdd(&g_done, 1);
        if (prev == Bc - 1) {
            float sp = 0.0f, sl = 0.0f;
            #pragma unroll
            for (int bb = 0; bb < Bc; bb++) {
                sp += *((volatile float*)&g_partial[bb * 2 + 0]);
                sl += *((volatile float*)&g_partial[bb * 2 + 1]);
            }
            out[0] = sp / (float)Bc;   // mean(push) * PUSH_W
            out[1] = sl / (float)Bc;   // mean(pull) * PULL_W
        }
    }
}

extern "C" void kernel_launch(void* const* d_in, const int* in_sizes, int n_in,
                              void* d_out, int out_size) {
    const int*   pos_inds     = (const int*)d_in[0];
    const int*   pos_gt_index = (const int*)d_in[1];
    const float* gt_bboxes    = (const float*)d_in[2];
    const float* bbox_preds   = (const float*)d_in[3];
    const float* cls_scores   = (const float*)d_in[4];
    const int*   gt_labels    = (const int*)d_in[5];
    float* out = (float*)d_out;

    cudaFuncSetAttribute(nms_loss_kernel,
                         cudaFuncAttributeMaxDynamicSharedMemorySize, SMEM_BYTES);

    gather_kernel<<<Bc, 256>>>(pos_inds, pos_gt_index, cls_scores, gt_labels);
    rank_kernel<<<dim3(32, Bc), 256>>>();
    adj_kernel<<<dim3(32, Bc), 256>>>(bbox_preds);
    nms_loss_kernel<<<Bc, NT, SMEM_BYTES>>>(pos_gt_index, gt_bboxes, bbox_preds, out);
}

// round 17
// speedup vs baseline: 1.2600x; 1.0156x over previous
#include <cuda_runtime.h>
#include <math.h>

#define Bc 8
#define Nc 1024
#define Mc 20000
#define Cc 80
#define Gc 64
#define NMS_THRf 0.5f
#define EPSf 1e-6f
#define FULL 0xffffffffu

#define NT 512      // nms_loss block size

// per-batch results: [b*2+0]=push_b, [b*2+1]=pull_b
__device__ float g_partial[Bc * 2];
__device__ int   g_done;
// adjacency bitmasks in RANK space, LOWER TRIANGLE only:
// row r, words w <= r>>5 valid; word w bit s <-> rank (w<<5)|s
__device__ unsigned g_adj[Bc * Nc * 32];
// gathered scores in ORIGINAL index space (linear)
__device__ float g_scores_orig[Bc * Nc];
// rank-permuted scores: g_scores[b][rank]
__device__ float g_scores[Bc * Nc];
// permutation: g_perm[b][rank] = original index
__device__ int g_perm[Bc * Nc];

__device__ __forceinline__ float iou_legacy(float4 a, float4 b, float area_a, float area_b) {
    float lx = fmaxf(a.x, b.x), ly = fmaxf(a.y, b.y);
    float rx = fminf(a.z, b.z), ry = fminf(a.w, b.w);
    float w = fmaxf(rx - lx + 1.0f, 0.0f), h = fmaxf(ry - ly + 1.0f, 0.0f);
    float ov = w * h;
    return ov / (area_a + area_b - ov);
}

// ---------------- score gather: one pass, high MLP ----------------
__global__ __launch_bounds__(256)
void gather_kernel(const int* __restrict__ pos_inds,
                   const int* __restrict__ pos_gt_index,
                   const float* __restrict__ cls_scores,
                   const int* __restrict__ gt_labels)
{
    const int b = blockIdx.x;
    const int tid = threadIdx.x;
    if (b == 0 && tid == 0) g_done = 0;
    int pi[4], gi[4];
    #pragma unroll
    for (int k = 0; k < 4; k++) {
        int n = tid + (k << 8);
        pi[k] = pos_inds[b * Nc + n];
        gi[k] = pos_gt_index[b * Nc + n];
    }
    int lbl[4];
    #pragma unroll
    for (int k = 0; k < 4; k++) lbl[k] = gt_labels[b * Gc + gi[k]];
    #pragma unroll
    for (int k = 0; k < 4; k++) {
        int n = tid + (k << 8);
        g_scores_orig[(b << 10) + n] =
            cls_scores[((size_t)b * Mc + pi[k]) * Cc + lbl[k]];
    }
}

// ---------------- rank: 32 blocks per batch, 4 rows per warp ----------------
__global__ __launch_bounds__(256)
void rank_kernel(void)
{
    __shared__ float ssc[Nc];
    const int b = blockIdx.y;
    {
        const float4* src = (const float4*)(g_scores_orig + (b << 10));
        float4* dst = (float4*)ssc;
        for (int p = threadIdx.x; p < Nc / 4; p += 256) dst[p] = src[p];
    }
    __syncthreads();

    const int wid = threadIdx.x >> 5, lane = threadIdx.x & 31;
    #pragma unroll
    for (int t = 0; t < 4; t++) {
        const int i = blockIdx.x * 32 + wid * 4 + t;
        const float si = ssc[i];
        int cnt = 0;
        #pragma unroll
        for (int w = 0; w < 32; w++) {
            int n = (w << 5) | lane;        // coalesced, conflict-free
            float sn = ssc[n];
            cnt += (sn > si) || (sn == si && n < i);
        }
        cnt = __reduce_add_sync(FULL, cnt);
        if (lane == 0) {
            g_perm[(b << 10) + cnt] = i;    // unique ranks -> no conflicts
            g_scores[(b << 10) + cnt] = si; // rank-permuted scores
        }
    }
}

// ---------------- lower-tri adjacency: 4 striped rows per warp ----------------
__global__ __launch_bounds__(256)
void adj_kernel(const float* __restrict__ bbox_preds)
{
    __shared__ float4 sb[Nc];
    __shared__ float  sa[Nc];
    const int b = blockIdx.y;
    const float4* bp = (const float4*)(bbox_preds + (size_t)b * Nc * 4);
    for (int n = threadIdx.x; n < Nc; n += 256) {
        int orig = g_perm[(b << 10) + n];
        float4 bx = bp[orig];
        sb[n] = bx;
        sa[n] = (bx.z - bx.x + 1.0f) * (bx.w - bx.y + 1.0f);
    }
    __syncthreads();

    const int wid = threadIdx.x >> 5, lane = threadIdx.x & 31;
    #pragma unroll
    for (int t = 0; t < 4; t++) {
        const int i = blockIdx.x * 8 + wid + (t << 8);   // striped rows: balance
        const int wi = i >> 5;
        const float4 bi = sb[i];
        const float ai = sa[i];
        unsigned* dst = g_adj + ((((size_t)b << 10) + i) << 5);
        for (int w = 0; w <= wi; w++) {     // lower triangle only
            int n = (w << 5) | lane;        // coalesced, conflict-free
            float v = iou_legacy(bi, sb[n], ai, sa[n]);
            unsigned bal = __ballot_sync(FULL, v > NMS_THRf && n != i);
            if (lane == 0) dst[w] = bal;
        }
    }
}

// ---------------- fixpoint + parallel loss: 1 block (512 thr) per batch ----------------
// smem adjacency is bank-swizzled: word w of row r lives at sadj[r*32 + (w^(r&31))]
// dynamic smem layout (bytes):
//   sboxA   float4[1024] @ 0       box coords                (16384)
//   sboxB   float4[1024] @ 16384   (area, score, gt, -)      (16384)
//   sadj    u32[1024*32] @ 32768   swizzled, lower-tri valid (131072)
//   sgtiou  float[64*64] @ 163840                            (16384)
//   skiller int[1024]    @ 180224                            (4096)
//   snpush  int[1024]    @ 184320                            (4096)
//   sfirst  int[64]      @ 188416                            (256)
//   skeptM  u32[32]      @ 188672                            (128)
//   sdeadM  u32[32]      @ 188800                            (128)
#define SMEM_BYTES 188928

extern __shared__ unsigned char smem_raw[];

__global__ __launch_bounds__(NT, 1)
void nms_loss_kernel(const int* __restrict__ pos_gt_index,
                     const float* __restrict__ gt_bboxes,
                     const float* __restrict__ bbox_preds,
                     float* __restrict__ out)
{
    float4*   sboxA   = (float4*)(smem_raw);
    float4*   sboxB   = (float4*)(smem_raw + 16384);
    unsigned* sadj    = (unsigned*)(smem_raw + 32768);
    float*    sgtiou  = (float*)(smem_raw + 163840);
    int*      skiller = (int*)(smem_raw + 180224);
    int*      snpush  = (int*)(smem_raw + 184320);
    int*      sfirst  = (int*)(smem_raw + 188416);
    unsigned* skeptM  = (unsigned*)(smem_raw + 188672);
    unsigned* sdeadM  = (unsigned*)(smem_raw + 188800);

    __shared__ int   s_lastr;
    __shared__ float s_pull, s_push;
    __shared__ int   s_pcnt, s_qcnt;

    const int b = blockIdx.x;
    const int tid = threadIdx.x;

    // ---- setup: permuted arrays by rank ----
    const float4* bp = (const float4*)(bbox_preds + (size_t)b * Nc * 4);
    for (int r = tid; r < Nc; r += NT) {
        int orig = g_perm[(b << 10) + r];
        float4 bx = bp[orig];
        sboxA[r] = bx;
        float area = (bx.z - bx.x + 1.0f) * (bx.w - bx.y + 1.0f);
        float sc = g_scores[(b << 10) + r];           // rank-permuted already
        int gi = pos_gt_index[b * Nc + orig];
        sboxB[r] = make_float4(area, sc, __int_as_float(gi), 0.0f);
        snpush[r] = 0;
    }
    const float4* gb = (const float4*)(gt_bboxes + (size_t)b * Gc * 4);
    for (int p = tid; p < Gc * Gc; p += NT) {
        int g1 = p >> 6, g2 = p & 63;
        float4 a = gb[g1];
        float4 c = gb[g2];
        float a1 = (a.z - a.x + 1.0f) * (a.w - a.y + 1.0f);
        float a2 = (c.z - c.x + 1.0f) * (c.w - c.y + 1.0f);
        sgtiou[p] = iou_legacy(a, c, a1, a2);
    }
    for (int g = tid; g < Gc; g += NT) sfirst[g] = 1 << 30;
    // swizzled copy of lower-triangle adjacency (~66KB)
    {
        const uint4* asrc4 = (const uint4*)(g_adj + ((size_t)b << 15));
        for (int idx = tid; idx < Nc * 8; idx += NT) {
            int r = idx >> 3, q = idx & 7;
            if ((q << 2) <= (r >> 5)) {                // quad overlaps lower tri
                uint4 v = asrc4[idx];
                int w0 = q << 2, x = r & 31;
                int base = r << 5;
                sadj[base + ((w0 + 0) ^ x)] = v.x;
                sadj[base + ((w0 + 1) ^ x)] = v.y;
                sadj[base + ((w0 + 2) ^ x)] = v.z;
                sadj[base + ((w0 + 3) ^ x)] = v.w;
            }
        }
    }
    if (tid < 32) { skeptM[tid] = 0u; sdeadM[tid] = 0u; }
    if (tid == 0) { s_pull = 0.0f; s_push = 0.0f; s_pcnt = 0; s_qcnt = 0; }
    __syncthreads();

    // ---- Phase 1: multi-sweep parallel-round NMS fixpoint ----
    // n DEAD <=> some KEPT lower-rank neighbor; n KEPT <=> all lower dead.
    // 4 sweeps per barrier: smem atomicOr results are visible to later sweeps
    // within the round (SM-local, coherent), so up to 4 DAG levels propagate
    // per barrier. Monotone lattice => stale reads safe, fixpoint identical.
    {
        bool decided[2] = {false, false};
        while (true) {
            #pragma unroll 1
            for (int sweep = 0; sweep < 4; sweep++) {
                #pragma unroll
                for (int k = 0; k < 2; k++) {
                    if (decided[k]) continue;
                    int n = tid + (k << 9);
                    int wn = n >> 5, sn = n & 31;
                    int base = n << 5;
                    unsigned dead_or = 0u, undec_or = 0u;
                    for (int w = 0; w < wn; w++) {       // independent LDS
                        unsigned r = sadj[base + (w ^ sn)];
                        unsigned kp = skeptM[w], dd = sdeadM[w];
                        dead_or  |= r & kp;
                        undec_or |= r & ~(kp | dd);
                    }
                    {                                     // partial word wn
                        unsigned r = sadj[base + (wn ^ sn)] & (sn ? ((1u << sn) - 1u) : 0u);
                        unsigned kp = skeptM[wn], dd = sdeadM[wn];
                        dead_or  |= r & kp;
                        undec_or |= r & ~(kp | dd);
                    }
                    if (dead_or) {
                        atomicOr(&sdeadM[wn], 1u << sn);
                        decided[k] = true;
                    } else if (!undec_or) {
                        atomicOr(&skeptM[wn], 1u << sn);
                        decided[k] = true;
                    }
                }
            }
            if (!__syncthreads_or((!decided[0]) || (!decided[1]))) break;
        }
    }
    if (tid == 0) {                          // lastr = highest-rank kept box
        int lastr = 0;
        for (int w = 31; w >= 0; w--) {
            if (skeptM[w]) { lastr = (w << 5) | (31 - __clz(skeptM[w])); break; }
        }
        s_lastr = lastr;
    }
    __syncthreads();

    const int lastr = s_lastr;

    // ---- Phase 2a: recover killer(n) (lower words only); per-gt first; histogram ----
    // killer(n) = lowest-rank kept neighbor, always < n for dead boxes; kept
    // boxes have no kept neighbors at all (independent set, symmetric adj).
    int pred_last = 0;
    for (int n = tid; n < Nc; n += NT) {
        int base = n << 5, x = n & 31, wn = n >> 5;
        unsigned nz = 0u;
        for (int w = 0; w <= wn; w++) {      // independent conflict-free LDS
            unsigned m = sadj[base + (w ^ x)] & skeptM[w];
            nz |= (m != 0u) ? (1u << w) : 0u;
        }
        int kr = -1;
        if (nz) {
            int w = __ffs(nz) - 1;
            unsigned m = sadj[base + (w ^ x)] & skeptM[w];
            kr = (w << 5) | (__ffs(m) - 1);
        }
        skiller[n] = kr;
        if (kr < 0) {
            int g = __float_as_int(sboxB[n].z);
            atomicMin(&sfirst[g], n);
        } else {
            if (kr == lastr) pred_last = 1;
            int g = __float_as_int(sboxB[kr].z);
            int gn = __float_as_int(sboxB[n].z);
            if (gn != g) {
                float iouv = iou_legacy(sboxA[kr], sboxA[n], sboxB[kr].x, sboxB[n].x);
                if (iouv > sgtiou[(g << 6) + gn]) atomicAdd(&snpush[kr], 1);
            }
        }
    }
    int last_rem = __syncthreads_or(pred_last);   // barrier + OR

    // ---- Phase 2b: accumulate pull/push in parallel ----
    float lpull = 0.0f, lpush = 0.0f;
    int lpc = 0, lqc = 0;
    for (int n = tid; n < Nc; n += NT) {
        int kr = skiller[n];
        if (kr < 0) {
            int g = __float_as_int(sboxB[n].z);
            int prev = sfirst[g];
            if (prev < n) {
                lpc++;                                     // pcnt is ungated
                if (!(n == lastr && !last_rem)) {
                    float ms = fmaxf(iou_legacy(sboxA[prev], sboxA[n],
                                                sboxB[prev].x, sboxB[n].x), EPSf);
                    lpull += -__logf(1.0f - NMS_THRf + ms) * sboxB[n].y;
                }
            }
        } else {
            int g = __float_as_int(sboxB[kr].z);
            int gn = __float_as_int(sboxB[n].z);
            if (gn != g) {
                float iouv = iou_legacy(sboxA[kr], sboxA[n], sboxB[kr].x, sboxB[n].x);
                if (iouv > sgtiou[(g << 6) + gn]) {
                    lqc++;
                    lpush += -__logf(1.0f - iouv) * sboxB[n].y / (float)snpush[kr];
                }
            }
        }
    }
    #pragma unroll
    for (int off = 16; off > 0; off >>= 1) {
        lpull += __shfl_xor_sync(FULL, lpull, off);
        lpush += __shfl_xor_sync(FULL, lpush, off);
        lpc   += __shfl_xor_sync(FULL, lpc, off);
        lqc   += __shfl_xor_sync(FULL, lqc, off);
    }
    if ((tid & 31) == 0) {
        atomicAdd(&s_pull, lpull);
        atomicAdd(&s_push, lpush);
        atomicAdd(&s_pcnt, lpc);
        atomicAdd(&s_qcnt, lqc);
    }
    __syncthreads();

    // ---- finalize: last block sums per-batch partials ----
    if (tid == 0) {
        g_partial[b * 2 + 0] = s_push / ((float)s_qcnt + EPSf);
        g_partial[b * 2 + 1] = s_pull / ((float)s_pcnt + EPSf);
        __threadfence();
        int prev = atomicAdd(&g_done, 1);
        if (prev == Bc - 1) {
            float sp = 0.0f, sl = 0.0f;
            #pragma unroll
            for (int bb = 0; bb < Bc; bb++) {
                sp += *((volatile float*)&g_partial[bb * 2 + 0]);
                sl += *((volatile float*)&g_partial[bb * 2 + 1]);
            }
            out[0] = sp / (float)Bc;   // mean(push) * PUSH_W
            out[1] = sl / (float)Bc;   // mean(pull) * PULL_W
        }
    }
}

extern "C" void kernel_launch(void* const* d_in, const int* in_sizes, int n_in,
                              void* d_out, int out_size) {
    const int*   pos_inds     = (const int*)d_in[0];
    const int*   pos_gt_index = (const int*)d_in[1];
    const float* gt_bboxes    = (const float*)d_in[2];
    const float* bbox_preds   = (const float*)d_in[3];
    const float* cls_scores   = (const float*)d_in[4];
    const int*   gt_labels    = (const int*)d_in[5];
    float* out = (float*)d_out;

    cudaFuncSetAttribute(nms_loss_kernel,
                         cudaFuncAttributeMaxDynamicSharedMemorySize, SMEM_BYTES);

    gather_kernel<<<Bc, 256>>>(pos_inds, pos_gt_index, cls_scores, gt_labels);
    rank_kernel<<<dim3(32, Bc), 256>>>();
    adj_kernel<<<dim3(32, Bc), 256>>>(bbox_preds);
    nms_loss_kernel<<<Bc, NT, SMEM_BYTES>>>(pos_gt_index, gt_bboxes, bbox_preds, out);
}